// round 16
// baseline (speedup 1.0000x reference)
#include <cuda_runtime.h>
#include <cuda_fp16.h>
#include <cstdint>
#include <cstring>

// Problem constants
#define H 512
#define W 512
#define NDET 512
#define NSAMP 512
#define NCH 32          // B*C = 4*8
#define HW (H * W)

// Duplicated pixel-pair, channel-interleaved fp16 volume.
// Line for (y, xp) = 128 bytes = 32 x half2 { v(y,xp,c), v(y,xp+1,c) }.
__device__ static __half2 g_xt[HW * NCH];

// ---------------------------------------------------------------------------
// Pack kernel: (B,C,H,W) fp32 -> duplicated-pair interleaved fp16 lines.
// ---------------------------------------------------------------------------
__global__ void pack_kernel(const float* __restrict__ in) {
    __shared__ __half sh[130][NCH + 1];
    const int tid = threadIdx.x;
    const int seg = blockIdx.x;           // 0..3
    const int y   = blockIdx.y;           // 0..511
    const int X0  = seg * 128;

    for (int c = 0; c < NCH; ++c) {
        if (tid < 130) {
            int px = X0 + tid;
            float v = (px < W) ? in[c * HW + y * W + px] : 0.0f;
            sh[tid][c] = __float2half(v);
        }
    }
    __syncthreads();

    int4* __restrict__ gout = reinterpret_cast<int4*>(g_xt);
#pragma unroll
    for (int k = 0; k < 4; ++k) {
        int id  = tid + k * 256;
        int ll  = id >> 3;
        int jj  = id & 7;
        union { __half2 h[4]; int4 v; } u;
#pragma unroll
        for (int q = 0; q < 4; ++q)
            u.h[q] = __halves2half2(sh[ll][4 * jj + q], sh[ll + 1][4 * jj + q]);
        gout[(size_t)(y * W + X0 + ll) * 8 + jj] = u.v;
    }
}

// Exact in-loop validity predicate (must match loop arithmetic bit-for-bit).
__device__ __forceinline__ bool valid_s(int s, float nsn, float cs,
                                        float xt0, float yt0) {
    float sv = (float)s - 255.5f;
    float xs = fmaf(sv, nsn, xt0);
    float ys = fmaf(sv, cs, yt0);
    int x0 = __float2int_rd(xs);
    int y0 = __float2int_rd(ys);
    return ((unsigned)x0 <= (unsigned)(W - 2)) &
           ((unsigned)y0 <= (unsigned)(H - 2));
}

// 256-bit global load (Blackwell LDG.E.256) with compile-time byte offset.
template <int OFF>
__device__ __forceinline__ void ldg256(const void* p, float* r) {
    asm("ld.global.v8.f32 {%0,%1,%2,%3,%4,%5,%6,%7}, [%8+%9];"
        : "=f"(r[0]), "=f"(r[1]), "=f"(r[2]), "=f"(r[3]),
          "=f"(r[4]), "=f"(r[5]), "=f"(r[6]), "=f"(r[7])
        : "l"(p), "n"(OFF));
}

__device__ __forceinline__ __half2 f_as_h2(float x) {
    union { float f; __half2 h; } u; u.f = x; return u.h;
}

// Per-sample body: 1 coord/weight computation amortized over the warp's 8
// groups; 2 LDG.256 (rows y, y+1: 8 channels' (L,R) pairs each);
// 16 HFMA2 into half2 chunk accumulators c[0..7].
#define RADON_BODY()                                                       \
    do {                                                                   \
        float xs = fmaf(sv, nsn, xt0);                                     \
        float ys = fmaf(sv, cs, yt0);                                      \
        float fx = floorf(xs);                                             \
        float fy = floorf(ys);                                             \
        float wx = xs - fx;                                                \
        float wy = ys - fy;                                                \
        int cell = (int)fmaf(fy, 512.0f, fx);   /* in-bounds by interval */\
        const char* pa = basep + ((size_t)cell << 7);                      \
        float rA[8], rB[8];                                                \
        ldg256<0>(pa, rA);                                                 \
        ldg256<65536>(pa, rB);          /* +512 lines * 128 B */           \
        float omx = 1.0f - wx, omy = 1.0f - wy;                            \
        __half2 wa = __floats2half2_rn(omx * omy, wx * omy);               \
        __half2 wb = __floats2half2_rn(omx * wy,  wx * wy);                \
        _Pragma("unroll")                                                  \
        for (int k = 0; k < 8; ++k) {                                      \
            c[k] = __hfma2(f_as_h2(rA[k]), wa, c[k]);                      \
            c[k] = __hfma2(f_as_h2(rB[k]), wb, c[k]);                      \
        }                                                                  \
        sv += 8.0f;                                                        \
    } while (0)

#define RADON_FOLD()                                                       \
    do {                                                                   \
        _Pragma("unroll")                                                  \
        for (int k = 0; k < 8; ++k) {                                      \
            float2 f = __half22float2(c[k]);                               \
            accf[k] += f.x + f.y;                                          \
            c[k] = hz;                                                     \
        }                                                                  \
    } while (0)

// ---------------------------------------------------------------------------
// Radon forward projection.
// Warp = one (angle, detector) ray. lane = g*4+li; group g in [0,8) handles
// samples s ≡ g (mod 8); lane li in [0,4) owns channels 8li..8li+7 via one
// LDG.256 per row (4 lanes x 32B = one full 128B line per group).
// Valid-s interval once per ray (monotonicity => interior needs no clamp).
// fp16 corner-weight accumulation, chunks of 8 samples folded into fp32.
// ---------------------------------------------------------------------------
__global__ __launch_bounds__(256, 5) void radon_kernel(
    const float* __restrict__ angles, float* __restrict__ out, int A)
{
    const int a    = blockIdx.y;
    const int warp = threadIdx.x >> 5;
    const int lane = threadIdx.x & 31;
    const int t    = blockIdx.x * 8 + warp;     // detector index

    float ang = angles[a];
    float sn, cs;
    sincosf(ang, &sn, &cs);

    const float tv  = (float)t - 255.5f;
    const float xt0 = fmaf(tv, cs, 255.5f);
    const float yt0 = fmaf(tv, sn, 255.5f);
    const float nsn = -sn;

    // ---- valid s-interval for this ray (warp-uniform) ----
    float lo = -1e9f, hi = 1e9f;
    if (nsn > 0.f)      { lo = fmaxf(lo, (0.f   - xt0) / nsn);
                          hi = fminf(hi, (511.f - xt0) / nsn); }
    else if (nsn < 0.f) { lo = fmaxf(lo, (511.f - xt0) / nsn);
                          hi = fminf(hi, (0.f   - xt0) / nsn); }
    else if (!(xt0 >= 0.f && xt0 < 511.f)) { lo = 1.f; hi = 0.f; }
    if (cs > 0.f)       { lo = fmaxf(lo, (0.f   - yt0) / cs);
                          hi = fminf(hi, (511.f - yt0) / cs); }
    else if (cs < 0.f)  { lo = fmaxf(lo, (511.f - yt0) / cs);
                          hi = fminf(hi, (0.f   - yt0) / cs); }
    else if (!(yt0 >= 0.f && yt0 < 511.f)) { lo = 1.f; hi = 0.f; }

    lo = fmaxf(lo, -300.f);  hi = fminf(hi, 300.f);
    int s_lo = max(0,   (int)floorf(lo + 255.5f) - 2);
    int s_hi = min(511, (int)ceilf (hi + 255.5f) + 2);
    // exact fix-up against the in-loop predicate; monotone coords =>
    // every interior s is then valid (no per-sample clamp needed).
    while (s_lo <= s_hi && !valid_s(s_lo, nsn, cs, xt0, yt0)) ++s_lo;
    while (s_lo <= s_hi && !valid_s(s_hi, nsn, cs, xt0, yt0)) --s_hi;

    const int g  = lane >> 2;           // 0..7  (s-phase)
    const int li = lane & 3;            // 0..3  (channel octet)
    const char* basep = (const char*)g_xt + (li << 5);   // +32B per octet

    __half2 c[8];
    float accf[8];
    const __half2 hz = __float2half2_rn(0.0f);
#pragma unroll
    for (int k = 0; k < 8; ++k) { c[k] = hz; accf[k] = 0.f; }

    int s0 = s_lo + ((g - s_lo) & 7);   // first s >= s_lo with s == g (mod 8)
    if (s0 <= s_hi) {
        int nIters = ((s_hi - s0) >> 3) + 1;
        float sv = (float)s0 - 255.5f;  // exact; sv += 8.0f stays exact

        int i = 0;
        // main: chunks of 8 bodies (8 samples per fp16 chain), fold to fp32
        for (; i + 8 <= nIters; i += 8) {
            RADON_BODY(); RADON_BODY(); RADON_BODY(); RADON_BODY();
            RADON_BODY(); RADON_BODY(); RADON_BODY(); RADON_BODY();
            RADON_FOLD();
        }
        // tail
        for (; i < nIters; ++i) {
            RADON_BODY();
            RADON_FOLD();
        }
    }

    // Reduce over the 8 s-phase groups (lane bits 2,3,4)
#pragma unroll
    for (int m_ = 4; m_ <= 16; m_ <<= 1) {
#pragma unroll
        for (int k = 0; k < 8; ++k)
            accf[k] += __shfl_xor_sync(0xffffffffu, accf[k], m_);
    }

    // Lane (g, li) writes channel c = 8*li + g: one STG per lane.
    float v = accf[0];
#pragma unroll
    for (int k = 1; k < 8; ++k)
        if (g == k) v = accf[k];
    int ch = (li << 3) + g;
    out[(size_t)ch * A * NDET + (size_t)a * NDET + t] = v;
}

extern "C" void kernel_launch(void* const* d_in, const int* in_sizes, int n_in,
                              void* d_out, int out_size)
{
    const float* x      = (const float*)d_in[0];   // (4,8,512,512) f32
    const float* angles = (const float*)d_in[1];   // (A,) f32
    float* out          = (float*)d_out;           // (4,8,A,512) f32
    const int A = in_sizes[1];

    dim3 pgrid(4, H);
    pack_kernel<<<pgrid, 256>>>(x);

    dim3 grid(NDET / 8, A);
    radon_kernel<<<grid, 256>>>(angles, out, A);
}